// round 16
// baseline (speedup 1.0000x reference)
#include <cuda_runtime.h>
#include <cuda_fp16.h>
#include <math.h>

// ---------------------------------------------------------------------------
// VariationalLinear fused kernel, round 16 (sm_100a)
//   out(256,4096) = x @ W^T + b,  W = mu + softplus(rho)*eps_w, + analytic KL
//   (prior_mu=0, prior_sigma=0.1 folded as constants; validated R8)
//
// R16 = R15 with the cp.async visibility race fixed: wait_group is PER-THREAD,
// so cross-thread consumption of staged data requires wait -> __syncthreads ->
// read (R15 did wait -> read at loop bottom: rel_err 0.199). Ordering now:
//   iter c: wait_group 2 | __syncthreads | X STS/LDG | rPf(c+4) | MMA(c) | wgen(c+1)
// -> chunk c+1 complete BEFORE the barrier; chunk c+4 has ~3 chunk-times to
// land (decoupled DRAM lookahead, the theory under test).
//  - raw weights own the whole wait_group FIFO (1 group/chunk, RSTG=5)
//  - X staged LDG.128 -> reg -> STS.128, zero FIFO interaction (L2-resident)
//  - rest = R12 (82.85us): 512 thr, warp=m16, KC=16, Wg double-buffered,
//    one __syncthreads/chunk, ldmatrix, fp16 MMA/fp32 acc, red.v2 epilogue
// ---------------------------------------------------------------------------

#define BATCH   256
#define IN_F    4096
#define OUT_F   4096
#define NT      64
#define KSPLIT  4
#define KSEG    (IN_F / KSPLIT)    // 1024
#define KC      16
#define NCHUNK  (KSEG / KC)        // 64
#define XSTG    2
#define RSTG    5
#define XSH     24                 // X row stride (halves): 16 data + 8 pad
#define WSH     24                 // Wg row stride (halves)
#define THREADS 512

#define XS_BYTES  (BATCH * XSH * 2)     // 12288
#define RAW_FL    (3 * NT * KC)         // 3072 floats (mu, rho, epsw)
#define RAW_BYTES (RAW_FL * 4)          // 12288
#define WG_BYTES  (NT * WSH * 2)        // 3072
#define SMEM_BYTES (XSTG * XS_BYTES + RSTG * RAW_BYTES + 2 * WG_BYTES) // 92160

#define KL_C0  (-2.80258509299f)        // log(0.1) - 0.5

__device__ __align__(16) __half g_x_h[BATCH * IN_F];   // x in fp16, row-major

__device__ __forceinline__ void cp_async16(void* smem_dst, const void* gsrc) {
    unsigned saddr = (unsigned)__cvta_generic_to_shared(smem_dst);
    asm volatile("cp.async.cg.shared.global [%0], [%1], 16;"
                 :: "r"(saddr), "l"(gsrc));
}

__device__ __forceinline__ void ldsm_x4(unsigned& r0, unsigned& r1,
                                        unsigned& r2, unsigned& r3,
                                        unsigned saddr) {
    asm volatile("ldmatrix.sync.aligned.m8n8.x4.shared.b16 {%0,%1,%2,%3}, [%4];"
                 : "=r"(r0), "=r"(r1), "=r"(r2), "=r"(r3) : "r"(saddr));
}

__device__ __forceinline__ void mma_f16(float* c, const unsigned* a,
                                        unsigned b0, unsigned b1) {
    asm volatile(
        "mma.sync.aligned.m16n8k16.row.col.f32.f16.f16.f32 "
        "{%0,%1,%2,%3}, {%4,%5,%6,%7}, {%8,%9}, {%0,%1,%2,%3};"
        : "+f"(c[0]), "+f"(c[1]), "+f"(c[2]), "+f"(c[3])
        : "r"(a[0]), "r"(a[1]), "r"(a[2]), "r"(a[3]), "r"(b0), "r"(b1));
}

__device__ __forceinline__ void red_v2(float* gptr, float v0, float v1) {
    asm volatile("red.global.add.v2.f32 [%0], {%1, %2};"
                 :: "l"(gptr), "f"(v0), "f"(v1) : "memory");
}

__device__ __forceinline__ float softplus_fast(float r) {
    return (r > 15.f) ? r : __logf(1.f + __expf(r));
}

// ---------------------------------------------------------------------------
// Prep: out <- bias broadcast, KL slot <- 0, x -> fp16 scratch.
// ---------------------------------------------------------------------------
__global__ void vl_prep(const float* __restrict__ x,
                        const float* __restrict__ bmu,
                        const float* __restrict__ brho,
                        const float* __restrict__ epsb,
                        float* __restrict__ out, int out_size) {
    int i = blockIdx.x * blockDim.x + threadIdx.x;
    if (i < BATCH * OUT_F) {
        int col = i & (OUT_F - 1);
        out[i] = fmaf(softplus_fast(brho[col]), epsb[col], bmu[col]);
    } else if (i < out_size) {
        out[i] = 0.f;
    }
    if (i < BATCH * IN_F)
        g_x_h[i] = __float2half_rn(x[i]);
}

// ---------------------------------------------------------------------------
// Main fused kernel: 512 threads, warp owns one m16 tile; deep raw lookahead
// ---------------------------------------------------------------------------
__global__ void __launch_bounds__(THREADS, 2)
vl_main(const float* __restrict__ mu, const float* __restrict__ rho,
        const float* __restrict__ epsw,
        float* __restrict__ out, float* __restrict__ klout) {
    extern __shared__ char smbase[];
    __half* Xs  = (__half*)smbase;                               // [2][256][XSH]
    float*  Raw = (float*)(smbase + XSTG * XS_BYTES);            // [5][3][1024]
    __shared__ float klred[16];

    const unsigned sbase = (unsigned)__cvta_generic_to_shared(smbase);
    const unsigned xs_b  = sbase;
    const unsigned wg_b  = sbase + XSTG * XS_BYTES + RSTG * RAW_BYTES;

    const int tid  = threadIdx.x;
    const int warp = tid >> 5;                 // 0..15
    const int lane = tid & 31;
    const int g    = lane >> 2;
    const int t    = lane & 3;

    const int ntile = blockIdx.x >> 2;
    const int kseg  = blockIdx.x & 3;
    const int n0    = ntile * NT;
    const int kbase = kseg * KSEG;
    const int m16   = warp * 16;

    float acc[8][4];
#pragma unroll
    for (int nt = 0; nt < 8; nt++)
#pragma unroll
        for (int i = 0; i < 4; i++) acc[nt][i] = 0.f;

    float klsum = 0.f;

    // Wgen: thread owns 2 consecutive elements of the 64x16 tile
    const int we   = tid * 2;                  // 0..1022
    const int wrow = we >> 4;                  // 0..63
    const int wk   = we & 15;

    // raw staging: op1 (all threads) covers streams 0,1; op2 (tid<256) stream 2
    const int  rs0  = tid >> 8;                // 0..1
    const int  ri0  = tid & 255;
    const long rg0  = (long)(n0 + (ri0 >> 2)) * IN_F + kbase + (ri0 & 3) * 4;
    const long rg1  = (long)(n0 + (tid >> 2)) * IN_F + kbase + (tid & 3) * 4;
    const float* streams[3] = { mu, rho, epsw };

    // X staging: one float4 per thread per chunk (LDG -> regs -> STS)
    const int  xrow = tid >> 1;                // 0..255
    const int  xseg = tid & 1;                 // 0..1 (8 halves each)
    const __half* xg = g_x_h + (long)xrow * IN_F + kbase + xseg * 8;
    __half* xsm = Xs + xrow * XSH + xseg * 8;  // + stage offset in halves

    // A ldmatrix offset (bytes): row = m16 + (lane&15), kofs = (lane>>4)*8
    const unsigned a_off =
        ((m16 + (lane & 15)) * XSH + ((lane >> 4) << 3)) * 2;
    // B ldmatrix base offset (pair p=0)
    const unsigned b_off0 =
        ((((lane >> 4) << 3) + (lane & 7)) * WSH + (((lane >> 3) & 1) << 3)) * 2;

    auto rPf = [&](int c) {                    // weights chunk c -> stage c%5
        if (c < NCHUNK) {
            float* rd = Raw + (c % RSTG) * RAW_FL;
            const int k0 = c * KC;
            cp_async16(rd + rs0 * (NT * KC) + ri0 * 4,
                       streams[rs0] + rg0 + k0);
            if (tid < 256)
                cp_async16(rd + 2 * (NT * KC) + tid * 4,
                           streams[2] + rg1 + k0);
        }
        asm volatile("cp.async.commit_group;");  // always: FIFO accounting
    };

    // Wgen(k): raw stage k%5 -> Wg[k&1]; KL with prior constants folded.
    // PRECONDITION: chunk k's cp.asyncs completed before the last barrier.
    auto wgen = [&](int k) {
        const float* rb = Raw + (k % RSTG) * RAW_FL;
        float2 m2 = *reinterpret_cast<const float2*>(rb + 0 * NT * KC + we);
        float2 r2 = *reinterpret_cast<const float2*>(rb + 1 * NT * KC + we);
        float2 e2 = *reinterpret_cast<const float2*>(rb + 2 * NT * KC + we);
        const float mv[2] = {m2.x, m2.y};
        const float rv[2] = {r2.x, r2.y};
        const float ev[2] = {e2.x, e2.y};
        float wv[2];
#pragma unroll
        for (int q = 0; q < 2; q++) {
            float sg = __logf(1.f + __expf(rv[q]));    // softplus
            wv[q] = fmaf(sg, ev[q], mv[q]);
            klsum += fmaf(50.f, fmaf(sg, sg, mv[q] * mv[q]),
                          KL_C0 - __logf(sg));
        }
        __half2 p0 = __floats2half2_rn(wv[0], wv[1]);
        *reinterpret_cast<__half2*>(
            (__half*)(smbase + XSTG * XS_BYTES + RSTG * RAW_BYTES)
            + (k & 1) * (NT * WSH) + wrow * WSH + wk) = p0;
    };

    // ---- prologue ----
    float4 xr = *reinterpret_cast<const float4*>(xg);          // X(0)
    rPf(0);                                    // commit chunks 0..3
    rPf(1);
    rPf(2);
    rPf(3);
    *reinterpret_cast<float4*>(xsm) = xr;      // stage 0 <- X(0)
    xr = *reinterpret_cast<const float4*>(xg + KC);            // X(1)
    asm volatile("cp.async.wait_group 3;");    // chunk 0 landed (this thread)
    __syncthreads();                           // chunk 0 visible to ALL
    wgen(0);                                   // -> Wg[0]
    // loop-top barrier publishes Xs stage 0 + Wg[0]

    for (int c = 0; c < NCHUNK; c++) {
        // chunks 0..c+3 committed; ensure 0..c+1 complete (2 left in flight)
        asm volatile("cp.async.wait_group 2;");
        __syncthreads();   // publishes: X stage c&1, Wg[c&1], raw chunk c+1

        // ---- X pipeline: STS X(c+1), LDG X(c+2) ----
        if (c + 1 < NCHUNK)
            *reinterpret_cast<float4*>(
                xsm + ((c + 1) & 1) * (BATCH * XSH)) = xr;
        if (c + 2 < NCHUNK)
            xr = *reinterpret_cast<const float4*>(xg + (c + 2) * KC);

        rPf(c + 4);                              // stage (c+4)%5, read @ c+3

        // ---- MMA(c): tensor burst ----
        const unsigned xa = xs_b + (c & 1) * XS_BYTES + a_off;
        unsigned a0[4];
        ldsm_x4(a0[0], a0[1], a0[2], a0[3], xa);

        const unsigned wb = wg_b + (c & 1) * WG_BYTES + b_off0;
#pragma unroll
        for (int p = 0; p < 4; p++) {
            unsigned b0, b1, b2, b3;
            ldsm_x4(b0, b1, b2, b3, wb + p * 16 * WSH * 2);
            mma_f16(acc[2 * p],     a0, b0, b1);
            mma_f16(acc[2 * p + 1], a0, b2, b3);
        }

        // ---- wgen(c+1): reads barrier-published chunk c+1; MUFU overlaps ----
        if (c + 1 < NCHUNK) wgen(c + 1);
    }

    // ---- epilogue: vector reductions (bias already in out) ----
    {
        int r0 = m16 + g;
#pragma unroll
        for (int nt = 0; nt < 8; nt++) {
            int col = n0 + nt * 8 + 2 * t;
            red_v2(&out[(long)r0 * OUT_F + col],       acc[nt][0], acc[nt][1]);
            red_v2(&out[(long)(r0 + 8) * OUT_F + col], acc[nt][2], acc[nt][3]);
        }
    }

    // ---- KL reduction ----
#pragma unroll
    for (int o = 16; o; o >>= 1)
        klsum += __shfl_xor_sync(0xFFFFFFFFu, klsum, o);
    if (lane == 0) klred[warp] = klsum;
    __syncthreads();
    if (tid == 0) {
        float s = 0.f;
#pragma unroll
        for (int i = 0; i < 16; i++) s += klred[i];
        atomicAdd(klout, s);
    }
}

// ---------------------------------------------------------------------------
extern "C" void kernel_launch(void* const* d_in, const int* in_sizes, int n_in,
                              void* d_out, int out_size) {
    const float* x    = (const float*)d_in[0];
    const float* wmu  = (const float*)d_in[1];
    const float* wrho = (const float*)d_in[2];
    const float* bmu  = (const float*)d_in[3];
    const float* brho = (const float*)d_in[4];
    const float* epsw = (const float*)d_in[5];
    const float* epsb = (const float*)d_in[6];
    float* out = (float*)d_out;

    int n = BATCH * IN_F;
    if (out_size > n) n = out_size;
    vl_prep<<<(n + 255) / 256, 256>>>(x, bmu, brho, epsb, out, out_size);

    cudaFuncSetAttribute(vl_main, cudaFuncAttributeMaxDynamicSharedMemorySize,
                         SMEM_BYTES);
    vl_main<<<(OUT_F / NT) * KSPLIT, THREADS, SMEM_BYTES>>>(
        wmu, wrho, epsw, out, out + (out_size - 1));
}